// round 8
// baseline (speedup 1.0000x reference)
#include <cuda_runtime.h>
#include <math.h>

// Problem constants
#define R_    2048
#define C_    1024
#define NCH   8

// KF tiling: 32 row-groups x 8 col-quarters
#define KF_ROWS   64
#define KF_COLS   128
#define NRG       32
#define NCQ       8
#define NKF       (NRG * NCQ)      // 256 blocks
#define NK3       136              // 128 colch + 8 nnz blocks

// Scratch (no allocations allowed -> device globals)
__device__ float g_lq[R_ * NCH];             // log prod_ba(1-P)  64KB
__device__ float g_PT[64 * R_];              // P transposed [64][2048]  512KB
__device__ float g_pSel[128];                // K0 per-block sel partials
__device__ float g_Lpart[NCQ * NRG * 1024];  // [cq][rg][ch*128+c] 1MB
__device__ float g_dsPart[NCQ * R_];         // [cq][row] D row-sum partials 64KB
__device__ float g_ncolB[NCH * 16];          // [ch][cq*2+half] colch partials
__device__ float g_nnz[64];                  // nnz_ch_ba
__device__ float g_psum[64];                 // sum_r P per (ch,ba)
__device__ unsigned int g_count = 0;         // K3 ticket (self-resetting)

// ---------------------------------------------------------------------------
// K0: softmax. 128 blocks x 256 thr, 16 rows/block (8 warps x 2 rows).
// Writes P (row-major, into out), PT (transposed), g_lq, sel partials.
// ---------------------------------------------------------------------------
__global__ __launch_bounds__(256) void k0_softmax(const float* __restrict__ W,
                                                  const float* __restrict__ G,
                                                  float* __restrict__ out)
{
    __shared__ float sP[16][64];
    __shared__ float sSel[16];

    const int t    = threadIdx.x;
    const int wid  = t >> 5;
    const int lane = t & 31;
    const int r0   = blockIdx.x * 16;

    const float2* W2 = reinterpret_cast<const float2*>(W);
    const float2* G2 = reinterpret_cast<const float2*>(G);

    #pragma unroll
    for (int rr = 0; rr < 2; rr++) {
        const int rl = wid * 2 + rr;
        const int r  = r0 + rl;

        float2 w  = W2[r * 32 + lane];
        float2 gv = G2[r * 32 + lane];
        float e0 = w.x + gv.x;
        float e1 = w.y + gv.y;

        float m = fmaxf(e0, e1);
        #pragma unroll
        for (int o = 16; o > 0; o >>= 1)
            m = fmaxf(m, __shfl_xor_sync(0xFFFFFFFFu, m, o));

        float x0 = expf(e0 - m);
        float x1 = expf(e1 - m);
        float s  = x0 + x1;
        #pragma unroll
        for (int o = 16; o > 0; o >>= 1)
            s += __shfl_xor_sync(0xFFFFFFFFu, s, o);

        const float inv = 1.0f / s;      // == max(P): exp(0)=1 at the argmax
        const float p0  = x0 * inv;
        const float p1  = x1 * inv;

        reinterpret_cast<float2*>(out)[r * 32 + lane] = make_float2(p0, p1);
        sP[rl][2 * lane]     = p0;
        sP[rl][2 * lane + 1] = p1;

        float lq = log1pf(-p0) + log1pf(-p1);
        lq += __shfl_xor_sync(0xFFFFFFFFu, lq, 1);
        lq += __shfl_xor_sync(0xFFFFFFFFu, lq, 2);
        if ((lane & 3) == 0) g_lq[r * NCH + (lane >> 2)] = lq;
        if (lane == 0) sSel[rl] = (inv > 0.99f) ? 1.0f : 0.0f;
    }
    __syncthreads();

    // transposed P: thread (i = t>>2, k = t&3) writes PT[i][r0 + 4k .. +3]
    {
        const int i = t >> 2;
        const int k = (t & 3) * 4;
        float4 v = make_float4(sP[k][i], sP[k + 1][i], sP[k + 2][i], sP[k + 3][i]);
        *reinterpret_cast<float4*>(&g_PT[i * R_ + r0 + k]) = v;
    }
    if (t == 0) {
        float v = 0.f;
        #pragma unroll
        for (int rl = 0; rl < 16; rl++) v += sSel[rl];
        g_pSel[blockIdx.x] = v;
    }
}

// ---------------------------------------------------------------------------
// KF: 256 blocks x 256 thr. Block (rg, cq) owns 64 rows x 128 cols of D.
// Thread (q = t&31 col-quad, rgl = t>>5 row subgroup of 8): 8 float4 D loads,
// 8ch x 4col accumulators, per-row partial sums. Cross-rowgroup reduction via
// smem, then write Lpart (32 partials per output) + dsPart.
// ---------------------------------------------------------------------------
__global__ __launch_bounds__(256) void kf_stream(const float* __restrict__ D)
{
    __shared__ float  slq[KF_ROWS][NCH];      // 2KB
    __shared__ float4 sacc4[8][256];          // 32KB: [rgl][ch*32+q]

    const int t   = threadIdx.x;
    const int q   = t & 31;
    const int rgl = t >> 5;
    const int cq  = blockIdx.x & 7;
    const int rg  = blockIdx.x >> 3;
    const int r0  = rg * KF_ROWS;

    // stage lq tile (64 rows x 8 ch = 512 floats)
    if (t < 128)
        reinterpret_cast<float4*>(&slq[0][0])[t] =
            reinterpret_cast<const float4*>(&g_lq[r0 * NCH])[t];
    __syncthreads();

    float acc[NCH][4];
    #pragma unroll
    for (int ch = 0; ch < NCH; ch++)
        #pragma unroll
        for (int k = 0; k < 4; k++) acc[ch][k] = 0.f;
    float dsv[8];

    const float4* D4 = reinterpret_cast<const float4*>(D);
    #pragma unroll
    for (int j = 0; j < 8; j++) {
        const int rl = rgl * 8 + j;
        float4 d = D4[(size_t)(r0 + rl) * 256 + cq * 32 + q];
        dsv[j] = (d.x + d.y) + (d.z + d.w);
        const float4 l0 = *reinterpret_cast<const float4*>(&slq[rl][0]);
        const float4 l1 = *reinterpret_cast<const float4*>(&slq[rl][4]);
        acc[0][0] = fmaf(d.x, l0.x, acc[0][0]); acc[0][1] = fmaf(d.y, l0.x, acc[0][1]);
        acc[0][2] = fmaf(d.z, l0.x, acc[0][2]); acc[0][3] = fmaf(d.w, l0.x, acc[0][3]);
        acc[1][0] = fmaf(d.x, l0.y, acc[1][0]); acc[1][1] = fmaf(d.y, l0.y, acc[1][1]);
        acc[1][2] = fmaf(d.z, l0.y, acc[1][2]); acc[1][3] = fmaf(d.w, l0.y, acc[1][3]);
        acc[2][0] = fmaf(d.x, l0.z, acc[2][0]); acc[2][1] = fmaf(d.y, l0.z, acc[2][1]);
        acc[2][2] = fmaf(d.z, l0.z, acc[2][2]); acc[2][3] = fmaf(d.w, l0.z, acc[2][3]);
        acc[3][0] = fmaf(d.x, l0.w, acc[3][0]); acc[3][1] = fmaf(d.y, l0.w, acc[3][1]);
        acc[3][2] = fmaf(d.z, l0.w, acc[3][2]); acc[3][3] = fmaf(d.w, l0.w, acc[3][3]);
        acc[4][0] = fmaf(d.x, l1.x, acc[4][0]); acc[4][1] = fmaf(d.y, l1.x, acc[4][1]);
        acc[4][2] = fmaf(d.z, l1.x, acc[4][2]); acc[4][3] = fmaf(d.w, l1.x, acc[4][3]);
        acc[5][0] = fmaf(d.x, l1.y, acc[5][0]); acc[5][1] = fmaf(d.y, l1.y, acc[5][1]);
        acc[5][2] = fmaf(d.z, l1.y, acc[5][2]); acc[5][3] = fmaf(d.w, l1.y, acc[5][3]);
        acc[6][0] = fmaf(d.x, l1.z, acc[6][0]); acc[6][1] = fmaf(d.y, l1.z, acc[6][1]);
        acc[6][2] = fmaf(d.z, l1.z, acc[6][2]); acc[6][3] = fmaf(d.w, l1.z, acc[6][3]);
        acc[7][0] = fmaf(d.x, l1.w, acc[7][0]); acc[7][1] = fmaf(d.y, l1.w, acc[7][1]);
        acc[7][2] = fmaf(d.z, l1.w, acc[7][2]); acc[7][3] = fmaf(d.w, l1.w, acc[7][3]);
    }

    // ds partials: all lanes of a warp share rgl; warp-reduce each row
    #pragma unroll
    for (int j = 0; j < 8; j++) {
        float v = dsv[j];
        #pragma unroll
        for (int o = 16; o > 0; o >>= 1)
            v += __shfl_xor_sync(0xFFFFFFFFu, v, o);
        if (q == 0) g_dsPart[cq * R_ + r0 + rgl * 8 + j] = v;
    }

    // cross-rowgroup reduction via smem
    #pragma unroll
    for (int ch = 0; ch < NCH; ch++)
        sacc4[rgl][ch * 32 + q] =
            make_float4(acc[ch][0], acc[ch][1], acc[ch][2], acc[ch][3]);
    __syncthreads();

    float4 L = sacc4[0][t];
    #pragma unroll
    for (int g = 1; g < 8; g++) {
        float4 v = sacc4[g][t];
        L.x += v.x; L.y += v.y; L.z += v.z; L.w += v.w;
    }
    reinterpret_cast<float4*>(g_Lpart)[(cq * NRG + rg) * 256 + t] = L;
}

// ---------------------------------------------------------------------------
// K3: 136 blocks x 256 thr.
//  Blocks 0..127: colch. Block (cq, ch, half): 64 outputs, sum 32 partials
//                 (4 pgroups x 8, stride 4KB, coalesced), colch=1-exp, ncol.
//  Blocks 128..135: nnz/psum. Warp per (ch,ba) column: dot(PT row, ds) with
//                 ds staged in smem from the 8 dsPart quarters.
//  Last-ticket block finalizes all scalars (all reads smem-staged).
// Output layout: P[131072] | tot[8] | max_nnz[8] | num_col[8] | num_row[8] |
//                nnz_ch_ba[64] | col_density[8] | num_row_sel[1]
// ---------------------------------------------------------------------------
__global__ __launch_bounds__(256) void k3_final(float* __restrict__ out)
{
    const int b    = blockIdx.x;
    const int t    = threadIdx.x;
    const int lane = t & 31;
    const int wid  = t >> 5;

    if (b < 128) {
        // ---- colch ----
        const int cq   = b >> 4;
        const int ch   = (b & 15) >> 1;
        const int half = b & 1;
        const int cl   = t & 63;
        const int pg   = t >> 6;            // 0..3

        const float* base = g_Lpart + (size_t)(cq * NRG + pg * 8) * 1024
                          + ch * 128 + half * 64 + cl;
        float a0 = base[0 * 1024], a1 = base[1 * 1024];
        float a2 = base[2 * 1024], a3 = base[3 * 1024];
        float a4 = base[4 * 1024], a5 = base[5 * 1024];
        float a6 = base[6 * 1024], a7 = base[7 * 1024];
        __shared__ float red[4][64];
        red[pg][cl] = ((a0 + a1) + (a2 + a3)) + ((a4 + a5) + (a6 + a7));
        __syncthreads();

        __shared__ float cs[2];
        if (t < 64) {
            float L = (red[0][t] + red[1][t]) + (red[2][t] + red[3][t]);
            float colch = 1.0f - expf(L);
            #pragma unroll
            for (int o = 16; o > 0; o >>= 1)
                colch += __shfl_xor_sync(0xFFFFFFFFu, colch, o);
            if (lane == 0) cs[t >> 5] = colch;
        }
        __syncthreads();
        if (t == 0) g_ncolB[ch * 16 + cq * 2 + half] = cs[0] + cs[1];
    } else {
        // ---- nnz / psum: 8 blocks x 8 warps = 64 outputs ----
        __shared__ float4 sds4[512];         // ds over all 2048 rows (8KB)
        // stage ds: thread sums the 8 cq quarters for its 8 rows
        {
            const float4* dsp4 = reinterpret_cast<const float4*>(g_dsPart);
            float4 v0 = make_float4(0.f, 0.f, 0.f, 0.f);
            float4 v1 = v0;
            #pragma unroll
            for (int cq = 0; cq < NCQ; cq++) {
                float4 a = dsp4[cq * 512 + t * 2];
                float4 c = dsp4[cq * 512 + t * 2 + 1];
                v0.x += a.x; v0.y += a.y; v0.z += a.z; v0.w += a.w;
                v1.x += c.x; v1.y += c.y; v1.z += c.z; v1.w += c.w;
            }
            sds4[t * 2]     = v0;
            sds4[t * 2 + 1] = v1;
        }
        __syncthreads();

        const int i = (b - 128) * 8 + wid;   // output column 0..63
        const float4* PT4 = reinterpret_cast<const float4*>(&g_PT[i * R_]);
        float an = 0.f, ap = 0.f;
        #pragma unroll
        for (int k = 0; k < 16; k++) {
            float4 p = PT4[k * 32 + lane];
            float4 d = sds4[k * 32 + lane];
            an += p.x * d.x + p.y * d.y + p.z * d.z + p.w * d.w;
            ap += (p.x + p.y) + (p.z + p.w);
        }
        #pragma unroll
        for (int o = 16; o > 0; o >>= 1) {
            an += __shfl_xor_sync(0xFFFFFFFFu, an, o);
            ap += __shfl_xor_sync(0xFFFFFFFFu, ap, o);
        }
        if (lane == 0) { g_nnz[i] = an; g_psum[i] = ap; }
    }

    // ---- completion ticket: last block finalizes ----
    __shared__ int isLast;
    __threadfence();
    if (t == 0) {
        unsigned int old = atomicAdd(&g_count, 1u);
        isLast = (old == NK3 - 1) ? 1 : 0;
        if (isLast) g_count = 0;             // reset for next graph replay
    }
    __syncthreads();
    if (!isLast) return;
    __threadfence();                          // acquire other blocks' writes

    __shared__ float snn[64], sps[64], snc[128], ssl[128];
    if (t < 64)  { snn[t] = g_nnz[t]; sps[t] = g_psum[t]; }
    if (t >= 64 && t < 192) snc[t - 64] = g_ncolB[t - 64];
    if (t >= 192)           ssl[t - 192] = g_pSel[t - 192];
    if (t < 64)  ssl[64 + t] = g_pSel[64 + t];   // remaining sel partials
    __syncthreads();

    if (t < 64) out[131104 + t] = snn[t];     // nnz_ch_ba

    if (t < NCH) {
        float m = -1e30f, ns = 0.f, rs = 0.f;
        #pragma unroll
        for (int ba = 0; ba < 8; ba++) {
            float nv = snn[t * 8 + ba];
            m  = fmaxf(m, nv);
            ns += nv;
            rs += sps[t * 8 + ba];
        }
        float ncl = 0.f;
        #pragma unroll
        for (int k = 0; k < 16; k++) ncl += snc[t * 16 + k];
        out[131072 + t] = m + ncl + rs;       // tot_ch
        out[131080 + t] = m;                  // max_nnz_ch
        out[131088 + t] = ncl;                // num_col_ch
        out[131096 + t] = rs;                 // num_row_ch
        out[131168 + t] = ns / rs / ncl;      // col_density_ch
    }
    if (t == 32) {                            // sel: warp 1 reduces 128 partials
        // done by a single thread over smem? use warp below instead
    }
    if (wid == 1) {
        float v = ssl[lane] + ssl[lane + 32] + ssl[lane + 64] + ssl[lane + 96];
        #pragma unroll
        for (int o = 16; o > 0; o >>= 1)
            v += __shfl_xor_sync(0xFFFFFFFFu, v, o);
        if (lane == 0) out[131176] = v;       // num_row_sel
    }
}

// ---------------------------------------------------------------------------
extern "C" void kernel_launch(void* const* d_in, const int* in_sizes, int n_in,
                              void* d_out, int out_size)
{
    const float* W = (const float*)d_in[0];   // [2048, 64]
    const float* D = (const float*)d_in[1];   // [2048, 1024]
    const float* G = (const float*)d_in[2];   // [2048, 64]
    // d_in[3] = i, unused by the math
    float* out = (float*)d_out;

    k0_softmax<<<128, 256>>>(W, G, out);
    kf_stream<<<NKF, 256>>>(D);
    k3_final<<<NK3, 256>>>(out);
}

// round 9
// speedup vs baseline: 1.0194x; 1.0194x over previous
#include <cuda_runtime.h>
#include <math.h>

// Problem constants
#define R_    2048
#define C_    1024
#define NCH   8

// KF tiling: 32 row-groups x 8 col-quarters, 64 rows x 128 cols per block
#define NRG   32
#define NCQ   8
#define NKF   (NRG * NCQ)          // 256 blocks
#define NK3   136                  // 128 colch blocks + 8 nnz/psum blocks

// Scratch (no allocations allowed -> device globals)
__device__ float g_Lpart[NCQ * NRG * 1024];  // [cq][rg][ch*128+c]  1MB
__device__ float g_pA[64 * NKF];             // [i][block256] partial sum_r P*s
__device__ float g_pB[64 * NRG];             // [i][rg32] partial sum_r P (cq=0)
__device__ float g_pSel[NRG];                // per-rg row-sel partials (cq=0)
__device__ float g_ncolB[NCH * 16];          // [ch][cq*2+half] colch partials
__device__ float g_nnz[64];                  // nnz_ch_ba
__device__ float g_psum[64];                 // sum_r P per (ch,ba)
__device__ float g_selv;                     // row-sel count
__device__ unsigned int g_count = 0;         // K3 ticket (self-resetting)

// ---------------------------------------------------------------------------
// KF: 256 blocks x 256 thr. Block (rg, cq) owns rows [rg*64, rg*64+64) and
// cols [cq*128, cq*128+128).
//  Stage A: 8 warps x 8 rows: softmax (redundant across cq; W/G hit L2 after
//           the first cq). P kept in registers; lq -> smem; cq==0 writes P,
//           pB partials, sel.
//  Stage B: stream the 64x128 D tile (float4/thread/row), 8ch x 4col accs,
//           per-row half-sums -> smem.
//  Stage C: cross-warp reduce -> Lpart (32 partials/output); in-block
//           pA partial = sum_rows P * s_half (linear in s -> sums exactly).
// ---------------------------------------------------------------------------
__global__ __launch_bounds__(256) void kf(const float* __restrict__ W,
                                          const float* __restrict__ D,
                                          const float* __restrict__ G,
                                          float* __restrict__ out)
{
    __shared__ float  slq[64][NCH];       // 2KB
    __shared__ float  sds[64];            // 256B
    __shared__ float  spa[8][64];         // 2KB
    __shared__ float  spb[8][64];         // 2KB (cq==0 only)
    __shared__ float  sSel[8];
    __shared__ float4 sacc4[8][256];      // 32KB

    const int t    = threadIdx.x;
    const int wid  = t >> 5;              // 0..7
    const int lane = t & 31;
    const int b    = blockIdx.x;
    const int cq   = b & 7;
    const int rg   = b >> 3;
    const int r0   = rg * 64;

    const float2* W2 = reinterpret_cast<const float2*>(W);
    const float2* G2 = reinterpret_cast<const float2*>(G);

    // ---- Stage A: softmax for rows r0 + wid*8 + j ----
    float p0r[8], p1r[8];
    float selcnt = 0.f;
    #pragma unroll
    for (int j = 0; j < 8; j++) {
        const int rl = wid * 8 + j;
        const int r  = r0 + rl;

        float2 w  = W2[r * 32 + lane];
        float2 gv = G2[r * 32 + lane];
        float e0 = w.x + gv.x;
        float e1 = w.y + gv.y;

        float m = fmaxf(e0, e1);
        #pragma unroll
        for (int o = 16; o > 0; o >>= 1)
            m = fmaxf(m, __shfl_xor_sync(0xFFFFFFFFu, m, o));

        float x0 = expf(e0 - m);
        float x1 = expf(e1 - m);
        float s  = x0 + x1;
        #pragma unroll
        for (int o = 16; o > 0; o >>= 1)
            s += __shfl_xor_sync(0xFFFFFFFFu, s, o);

        const float inv = 1.0f / s;       // == max(P): exp(0)=1 at the argmax
        const float p0  = x0 * inv;
        const float p1  = x1 * inv;
        p0r[j] = p0;
        p1r[j] = p1;

        if (cq == 0)
            reinterpret_cast<float2*>(out)[r * 32 + lane] = make_float2(p0, p1);

        float lq = log1pf(-p0) + log1pf(-p1);
        lq += __shfl_xor_sync(0xFFFFFFFFu, lq, 1);
        lq += __shfl_xor_sync(0xFFFFFFFFu, lq, 2);
        if ((lane & 3) == 0) slq[rl][lane >> 2] = lq;
        if (lane == 0) selcnt += (inv > 0.99f) ? 1.0f : 0.0f;
    }
    if (cq == 0) {
        if (lane == 0) sSel[wid] = selcnt;
        float b0 = 0.f, b1 = 0.f;
        #pragma unroll
        for (int j = 0; j < 8; j++) { b0 += p0r[j]; b1 += p1r[j]; }
        spb[wid][2 * lane]     = b0;
        spb[wid][2 * lane + 1] = b1;
    }
    __syncthreads();

    // ---- Stage B: stream D tile; warp wid covers rows wid*8..wid*8+7 ----
    float acc[NCH][4];
    #pragma unroll
    for (int ch = 0; ch < NCH; ch++)
        #pragma unroll
        for (int k = 0; k < 4; k++) acc[ch][k] = 0.f;
    float dsv[8];

    const float4* D4 = reinterpret_cast<const float4*>(D);
    #pragma unroll
    for (int j = 0; j < 8; j++) {
        const int rl = wid * 8 + j;
        float4 d = D4[(size_t)(r0 + rl) * 256 + cq * 32 + lane];
        dsv[j] = (d.x + d.y) + (d.z + d.w);
        const float4 l0 = *reinterpret_cast<const float4*>(&slq[rl][0]);
        const float4 l1 = *reinterpret_cast<const float4*>(&slq[rl][4]);
        acc[0][0] = fmaf(d.x, l0.x, acc[0][0]); acc[0][1] = fmaf(d.y, l0.x, acc[0][1]);
        acc[0][2] = fmaf(d.z, l0.x, acc[0][2]); acc[0][3] = fmaf(d.w, l0.x, acc[0][3]);
        acc[1][0] = fmaf(d.x, l0.y, acc[1][0]); acc[1][1] = fmaf(d.y, l0.y, acc[1][1]);
        acc[1][2] = fmaf(d.z, l0.y, acc[1][2]); acc[1][3] = fmaf(d.w, l0.y, acc[1][3]);
        acc[2][0] = fmaf(d.x, l0.z, acc[2][0]); acc[2][1] = fmaf(d.y, l0.z, acc[2][1]);
        acc[2][2] = fmaf(d.z, l0.z, acc[2][2]); acc[2][3] = fmaf(d.w, l0.z, acc[2][3]);
        acc[3][0] = fmaf(d.x, l0.w, acc[3][0]); acc[3][1] = fmaf(d.y, l0.w, acc[3][1]);
        acc[3][2] = fmaf(d.z, l0.w, acc[3][2]); acc[3][3] = fmaf(d.w, l0.w, acc[3][3]);
        acc[4][0] = fmaf(d.x, l1.x, acc[4][0]); acc[4][1] = fmaf(d.y, l1.x, acc[4][1]);
        acc[4][2] = fmaf(d.z, l1.x, acc[4][2]); acc[4][3] = fmaf(d.w, l1.x, acc[4][3]);
        acc[5][0] = fmaf(d.x, l1.y, acc[5][0]); acc[5][1] = fmaf(d.y, l1.y, acc[5][1]);
        acc[5][2] = fmaf(d.z, l1.y, acc[5][2]); acc[5][3] = fmaf(d.w, l1.y, acc[5][3]);
        acc[6][0] = fmaf(d.x, l1.z, acc[6][0]); acc[6][1] = fmaf(d.y, l1.z, acc[6][1]);
        acc[6][2] = fmaf(d.z, l1.z, acc[6][2]); acc[6][3] = fmaf(d.w, l1.z, acc[6][3]);
        acc[7][0] = fmaf(d.x, l1.w, acc[7][0]); acc[7][1] = fmaf(d.y, l1.w, acc[7][1]);
        acc[7][2] = fmaf(d.z, l1.w, acc[7][2]); acc[7][3] = fmaf(d.w, l1.w, acc[7][3]);
    }

    // per-row half-sums -> smem
    #pragma unroll
    for (int j = 0; j < 8; j++) {
        float v = dsv[j];
        #pragma unroll
        for (int o = 16; o > 0; o >>= 1)
            v += __shfl_xor_sync(0xFFFFFFFFu, v, o);
        if (lane == 0) sds[wid * 8 + j] = v;
    }

    // stage accs for cross-warp reduction
    #pragma unroll
    for (int ch = 0; ch < NCH; ch++)
        sacc4[wid][ch * 32 + lane] =
            make_float4(acc[ch][0], acc[ch][1], acc[ch][2], acc[ch][3]);
    __syncthreads();

    // ---- Stage C ----
    // Lpart: thread t = ch*32 + colquad
    {
        float4 L = sacc4[0][t];
        #pragma unroll
        for (int g = 1; g < 8; g++) {
            float4 v = sacc4[g][t];
            L.x += v.x; L.y += v.y; L.z += v.z; L.w += v.w;
        }
        reinterpret_cast<float4*>(g_Lpart)[(cq * NRG + rg) * 256 + t] = L;
    }

    // pA partial: warp wid owns rows wid*8..wid*8+7; lane holds i=2*lane, 2*lane+1
    {
        float pa0 = 0.f, pa1 = 0.f;
        #pragma unroll
        for (int j = 0; j < 8; j++) {
            const float s = sds[wid * 8 + j];     // smem broadcast
            pa0 = fmaf(p0r[j], s, pa0);
            pa1 = fmaf(p1r[j], s, pa1);
        }
        spa[wid][2 * lane]     = pa0;
        spa[wid][2 * lane + 1] = pa1;
    }
    __syncthreads();

    if (t < 64) {
        float a = 0.f;
        #pragma unroll
        for (int w2 = 0; w2 < 8; w2++) a += spa[w2][t];
        g_pA[t * NKF + b] = a;
        if (cq == 0) {
            float pb = 0.f;
            #pragma unroll
            for (int w2 = 0; w2 < 8; w2++) pb += spb[w2][t];
            g_pB[t * NRG + rg] = pb;
        }
    }
    if (cq == 0 && t == 0) {
        float v = 0.f;
        #pragma unroll
        for (int w2 = 0; w2 < 8; w2++) v += sSel[w2];
        g_pSel[rg] = v;
    }
}

// ---------------------------------------------------------------------------
// K3: 136 blocks x 256 thr.
//  Blocks 0..127: colch. Block (cq, ch, half): 64 outputs, 32 partials each,
//                 colch = 1-exp, ncol partial.
//  Blocks 128..135: nnz/psum/sel. Warp per output i: sum g_pA over 256 blocks
//                 (coalesced) and g_pB over 32.
//  Last-ticket block finalizes all scalars.
// Output layout: P[131072] | tot[8] | max_nnz[8] | num_col[8] | num_row[8] |
//                nnz_ch_ba[64] | col_density[8] | num_row_sel[1]
// ---------------------------------------------------------------------------
__global__ __launch_bounds__(256) void k3_final(float* __restrict__ out)
{
    const int b    = blockIdx.x;
    const int t    = threadIdx.x;
    const int lane = t & 31;
    const int wid  = t >> 5;

    if (b < 128) {
        // ---- colch ----
        const int cq   = b >> 4;
        const int ch   = (b & 15) >> 1;
        const int half = b & 1;
        const int cl   = t & 63;
        const int pg   = t >> 6;            // 0..3

        const float* base = g_Lpart + (size_t)(cq * NRG + pg * 8) * 1024
                          + ch * 128 + half * 64 + cl;
        float a0 = base[0 * 1024], a1 = base[1 * 1024];
        float a2 = base[2 * 1024], a3 = base[3 * 1024];
        float a4 = base[4 * 1024], a5 = base[5 * 1024];
        float a6 = base[6 * 1024], a7 = base[7 * 1024];
        __shared__ float red[4][64];
        red[pg][cl] = ((a0 + a1) + (a2 + a3)) + ((a4 + a5) + (a6 + a7));
        __syncthreads();

        __shared__ float cs[2];
        if (t < 64) {
            float L = (red[0][t] + red[1][t]) + (red[2][t] + red[3][t]);
            float colch = 1.0f - expf(L);
            #pragma unroll
            for (int o = 16; o > 0; o >>= 1)
                colch += __shfl_xor_sync(0xFFFFFFFFu, colch, o);
            if (lane == 0) cs[t >> 5] = colch;
        }
        __syncthreads();
        if (t == 0) g_ncolB[ch * 16 + cq * 2 + half] = cs[0] + cs[1];
    } else {
        // ---- nnz / psum: 8 blocks x 8 warps = 64 outputs ----
        const int i = (b - 128) * 8 + wid;
        float an = 0.f;
        #pragma unroll
        for (int k = 0; k < 8; k++)
            an += g_pA[i * NKF + lane + 32 * k];
        float ap = g_pB[i * NRG + lane];     // 32 values, one per lane
        #pragma unroll
        for (int o = 16; o > 0; o >>= 1) {
            an += __shfl_xor_sync(0xFFFFFFFFu, an, o);
            ap += __shfl_xor_sync(0xFFFFFFFFu, ap, o);
        }
        if (lane == 0) { g_nnz[i] = an; g_psum[i] = ap; }

        if (b == 128 && wid == 0) {          // sel: 32 partials
            float v = g_pSel[lane];
            #pragma unroll
            for (int o = 16; o > 0; o >>= 1)
                v += __shfl_xor_sync(0xFFFFFFFFu, v, o);
            if (lane == 0) g_selv = v;
        }
    }

    // ---- completion ticket: last block finalizes ----
    __shared__ int isLast;
    __threadfence();
    if (t == 0) {
        unsigned int old = atomicAdd(&g_count, 1u);
        isLast = (old == NK3 - 1) ? 1 : 0;
        if (isLast) g_count = 0;             // reset for next graph replay
    }
    __syncthreads();
    if (!isLast) return;
    __threadfence();                          // acquire other blocks' writes

    __shared__ float snn[64], sps[64], snc[128];
    if (t < 64)             { snn[t] = g_nnz[t]; sps[t] = g_psum[t]; }
    if (t >= 64 && t < 192)   snc[t - 64] = g_ncolB[t - 64];
    __syncthreads();

    if (t < 64) out[131104 + t] = snn[t];     // nnz_ch_ba

    if (t < NCH) {
        float m = -1e30f, ns = 0.f, rs = 0.f;
        #pragma unroll
        for (int ba = 0; ba < 8; ba++) {
            float nv = snn[t * 8 + ba];
            m  = fmaxf(m, nv);
            ns += nv;
            rs += sps[t * 8 + ba];
        }
        float ncl = 0.f;
        #pragma unroll
        for (int k = 0; k < 16; k++) ncl += snc[t * 16 + k];
        out[131072 + t] = m + ncl + rs;       // tot_ch
        out[131080 + t] = m;                  // max_nnz_ch
        out[131088 + t] = ncl;                // num_col_ch
        out[131096 + t] = rs;                 // num_row_ch
        out[131168 + t] = ns / rs / ncl;      // col_density_ch
    }
    if (t == 64) out[131176] = g_selv;        // num_row_sel
}

// ---------------------------------------------------------------------------
extern "C" void kernel_launch(void* const* d_in, const int* in_sizes, int n_in,
                              void* d_out, int out_size)
{
    const float* W = (const float*)d_in[0];   // [2048, 64]
    const float* D = (const float*)d_in[1];   // [2048, 1024]
    const float* G = (const float*)d_in[2];   // [2048, 64]
    // d_in[3] = i, unused by the math
    float* out = (float*)d_out;

    kf<<<NKF, 256>>>(W, D, G, out);
    k3_final<<<NK3, 256>>>(out);
}